// round 10
// baseline (speedup 1.0000x reference)
#include <cuda_runtime.h>
#include <cstdint>

#define N_NODES 100000
#define N_EDGES 3200000
#define IN_F    128

// ---------------- scratch (no allocations allowed) ----------------
__device__ float g_bufA[N_NODES * 32];   // node table A: y|r (layer1), later a|b (edge MLP)
__device__ float g_bufB[N_NODES * 32];   // node table B: y|r (layer2)
__device__ float g_agg[N_NODES * 16];    // neighbor-sum accumulator
__device__ float g_cnt[N_NODES];         // in-degree (float) — counted once, reused

// packed f32x2 FMA (Blackwell; ptxas never emits FFMA2 from C++)
__device__ __forceinline__ void ffma2(unsigned long long& d,
                                      unsigned long long a,
                                      unsigned long long b) {
    asm("fma.rn.f32x2 %0, %1, %2, %0;" : "+l"(d) : "l"(a), "l"(b));
}
__device__ __forceinline__ unsigned long long pack2(float v) {
    unsigned long long r;
    asm("mov.b64 %0, {%1, %1};" : "=l"(r) : "f"(v));
    return r;
}

// ---------------- kernels ----------------

__global__ void k_zero() {
    int i = blockIdx.x * blockDim.x + threadIdx.x;
    if (i < N_NODES * 16) g_agg[i] = 0.f;
    if (i < N_NODES)      g_cnt[i] = 0.f;
}

// y|r = x @ [w1_l | w1_r]   (128 -> 32), weights in shared, f32x2 packed FMA
__global__ void k_gemm_in(const float* __restrict__ x,
                          const float* __restrict__ wl,
                          const float* __restrict__ wr) {
    __shared__ float sw[IN_F * 32];
    for (int i = threadIdx.x; i < IN_F * 32; i += blockDim.x) {
        int k = i >> 5, c = i & 31;
        sw[i] = (c < 16) ? wl[k * 16 + c] : wr[k * 16 + (c - 16)];
    }
    __syncthreads();
    int n = blockIdx.x * blockDim.x + threadIdx.x;
    if (n >= N_NODES) return;

    unsigned long long acc2[16];
#pragma unroll
    for (int j = 0; j < 16; j++) acc2[j] = 0ull;

    const float4* xr = (const float4*)(x + (size_t)n * IN_F);
    const unsigned long long* sw2 = (const unsigned long long*)sw;

#pragma unroll 4
    for (int k4 = 0; k4 < IN_F / 4; k4++) {
        float4 xv = __ldg(xr + k4);
        float xs[4] = {xv.x, xv.y, xv.z, xv.w};
#pragma unroll
        for (int i = 0; i < 4; i++) {
            unsigned long long xx = pack2(xs[i]);
            int k = k4 * 4 + i;
#pragma unroll
            for (int j = 0; j < 16; j++)
                ffma2(acc2[j], xx, sw2[k * 16 + j]);   // uniform smem addr -> broadcast
        }
    }
    ulonglong2* o = (ulonglong2*)(g_bufA + (size_t)n * 32);
#pragma unroll
    for (int j = 0; j < 8; j++)
        o[j] = make_ulonglong2(acc2[2 * j], acc2[2 * j + 1]);
}

// edge scatter: 4 threads per edge, each does one 16B vector red to g_agg[dst]
// dir selects source node table (0: bufA, 1: bufB). addCnt only on layer 1.
__global__ void k_scatter(const int* __restrict__ ei, int dir, int addCnt) {
    const float* in = dir ? g_bufB : g_bufA;
    int t = blockIdx.x * blockDim.x + threadIdx.x;
    if (t >= N_EDGES * 4) return;
    int e = t >> 2, c = t & 3;
    int s = __ldg(ei + e);
    int d = __ldg(ei + N_EDGES + e);
    float4 v = *(const float4*)(in + (size_t)s * 32 + 4 * c);   // y part (cols 0..15)
    float* p = g_agg + (size_t)d * 16 + 4 * c;
    asm volatile("red.global.add.v4.f32 [%0], {%1,%2,%3,%4};"
                 :: "l"(p), "f"(v.x), "f"(v.y), "f"(v.z), "f"(v.w) : "memory");
    if (addCnt && c == 0) atomicAdd(g_cnt + d, 1.0f);
}

// Fused combine + 16->32 GEMM. One warp per node.
//   h = relu(agg/max(cnt,1) + bc + in[n][16:32])       (lanes 0..15)
//   out[n][lane] = sum_k h_k * sw[k][lane] (+bo on lanes 0..15)
// sw[k][c] = (c<16) ? wa[k][c] : wb[k+offB][c-16]
// dir=0: in=bufA out=bufB ; dir=1: in=bufB out=bufA. zeroAgg re-zeroes agg for next layer.
__global__ void k_comb(int dir,
                       const float* __restrict__ wa, const float* __restrict__ wb,
                       const float* __restrict__ bc, const float* __restrict__ bo,
                       int offB, int zeroAgg) {
    __shared__ float sw[16 * 32];
    __shared__ float sbc[16], sbo[16];
    const float* in  = dir ? g_bufB : g_bufA;
    float*       out = dir ? g_bufA : g_bufB;
    for (int i = threadIdx.x; i < 16 * 32; i += blockDim.x) {
        int k = i >> 5, c = i & 31;
        sw[i] = (c < 16) ? wa[k * 16 + c] : wb[(k + offB) * 16 + (c - 16)];
    }
    if (threadIdx.x < 16) {
        sbc[threadIdx.x] = bc[threadIdx.x];
        sbo[threadIdx.x] = bo ? bo[threadIdx.x] : 0.f;
    }
    __syncthreads();

    int w = (blockIdx.x * blockDim.x + threadIdx.x) >> 5;
    if (w >= N_NODES) return;
    int lane = threadIdx.x & 31;

    float h = 0.f;
    if (lane < 16) {
        float aggv = g_agg[(size_t)w * 16 + lane];
        float r    = in[(size_t)w * 32 + 16 + lane];
        float cnt  = fmaxf(g_cnt[w], 1.0f);          // same addr across lanes -> broadcast
        h = fmaxf(aggv / cnt + sbc[lane] + r, 0.f);
        if (zeroAgg) g_agg[(size_t)w * 16 + lane] = 0.f;
    }
    float o = (lane < 16) ? sbo[lane] : 0.f;
#pragma unroll
    for (int k = 0; k < 16; k++) {
        float hk = __shfl_sync(~0u, h, k);
        o = fmaf(hk, sw[k * 32 + lane], o);
    }
    out[(size_t)w * 32 + lane] = o;                  // coalesced 128B per warp
}

// per edge: z = relu(a[src] + b[dst]) ; o = z @ fc2 + fc2_b ; log_softmax
__global__ void k_edge(const int* __restrict__ ei,
                       const float* __restrict__ fc2w,
                       const float* __restrict__ fc2b,
                       float* __restrict__ out) {
    __shared__ float sf[34];
    if (threadIdx.x < 32) sf[threadIdx.x] = fc2w[threadIdx.x];
    if (threadIdx.x < 2)  sf[32 + threadIdx.x] = fc2b[threadIdx.x];
    __syncthreads();
    int e = blockIdx.x * blockDim.x + threadIdx.x;
    if (e >= N_EDGES) return;
    int s = __ldg(ei + e);
    int d = __ldg(ei + N_EDGES + e);
    const float4* ap = (const float4*)(g_bufA + (size_t)s * 32);       // a = h_s@fc1_top + fc1_b
    const float4* bp = (const float4*)(g_bufA + (size_t)d * 32 + 16);  // b = h_d@fc1_bot
    float o0 = sf[32], o1 = sf[33];
#pragma unroll
    for (int q = 0; q < 4; q++) {
        float4 a = ap[q];
        float4 b = bp[q];
        float z0 = fmaxf(a.x + b.x, 0.f);
        float z1 = fmaxf(a.y + b.y, 0.f);
        float z2 = fmaxf(a.z + b.z, 0.f);
        float z3 = fmaxf(a.w + b.w, 0.f);
        int j = q * 4;
        o0 = fmaf(z0, sf[(j + 0) * 2 + 0], o0);  o1 = fmaf(z0, sf[(j + 0) * 2 + 1], o1);
        o0 = fmaf(z1, sf[(j + 1) * 2 + 0], o0);  o1 = fmaf(z1, sf[(j + 1) * 2 + 1], o1);
        o0 = fmaf(z2, sf[(j + 2) * 2 + 0], o0);  o1 = fmaf(z2, sf[(j + 2) * 2 + 1], o1);
        o0 = fmaf(z3, sf[(j + 3) * 2 + 0], o0);  o1 = fmaf(z3, sf[(j + 3) * 2 + 1], o1);
    }
    float m = fmaxf(o0, o1);
    float l = m + __logf(__expf(o0 - m) + __expf(o1 - m));
    ((float2*)out)[e] = make_float2(o0 - l, o1 - l);
}

// ---------------- launch ----------------

extern "C" void kernel_launch(void* const* d_in, const int* in_sizes, int n_in,
                              void* d_out, int out_size) {
    const float* x    = (const float*)d_in[0];
    const int*   ei   = (const int*)  d_in[1];
    const float* w1l  = (const float*)d_in[2];
    const float* b1l  = (const float*)d_in[3];
    const float* w1r  = (const float*)d_in[4];
    const float* w2l  = (const float*)d_in[5];
    const float* b2l  = (const float*)d_in[6];
    const float* w2r  = (const float*)d_in[7];
    const float* fc1w = (const float*)d_in[8];
    const float* fc1b = (const float*)d_in[9];
    const float* fc2w = (const float*)d_in[10];
    const float* fc2b = (const float*)d_in[11];
    float* out = (float*)d_out;

    const int TB = 256;
    int gN16 = (N_NODES * 16 + TB - 1) / TB;   // 6250
    int gG   = (N_NODES + 127) / 128;          // 782
    int gE4  = (N_EDGES * 4 + TB - 1) / TB;    // 50000
    int gE   = (N_EDGES + TB - 1) / TB;        // 12500
    int gW   = (N_NODES * 32 + TB - 1) / TB;   // 12500 (warp per node)

    k_zero<<<gN16, TB>>>();
    // A = x @ [w1_l|w1_r]
    k_gemm_in<<<gG, 128>>>(x, w1l, w1r);
    // layer 1: scatter A.y -> agg (+cnt); combine -> relu -> @[w2_l|w2_r] -> B
    k_scatter<<<gE4, TB>>>(ei, 0, 1);
    k_comb<<<gW, TB>>>(0, w2l, w2r, b1l, nullptr, 0, 1);
    // layer 2: scatter B.y -> agg; combine -> relu -> @[fc1_top|fc1_bot](+fc1_b) -> A
    k_scatter<<<gE4, TB>>>(ei, 1, 0);
    k_comb<<<gW, TB>>>(1, fc1w, fc1w, b2l, fc1b, 16, 0);
    // per-edge head + log_softmax
    k_edge<<<gE, TB>>>(ei, fc2w, fc2b, out);
}

// round 12
// speedup vs baseline: 1.2421x; 1.2421x over previous
#include <cuda_runtime.h>
#include <cstdint>

#define N_NODES 100000
#define N_EDGES 3200000
#define IN_F    128

// ---------------- scratch (no allocations allowed) ----------------
__device__ float g_yr[N_NODES * 32];    // [n][0:16]=y (lin_l), [n][16:32]=r (lin_r); later a|b
__device__ float g_agg[N_NODES * 16];   // neighbor-sum accumulator
__device__ float g_cnt[N_NODES];        // in-degree (float)
__device__ float g_h[N_NODES * 16];     // hidden activations (h1 then h2)

// packed f32x2 FMA (Blackwell; ptxas never emits FFMA2 from C++)
__device__ __forceinline__ void ffma2(unsigned long long& d,
                                      unsigned long long a,
                                      unsigned long long b) {
    asm("fma.rn.f32x2 %0, %1, %2, %0;" : "+l"(d) : "l"(a), "l"(b));
}
__device__ __forceinline__ unsigned long long pack2(float v) {
    unsigned long long r;
    asm("mov.b64 %0, {%1, %1};" : "=l"(r) : "f"(v));
    return r;
}

// ---------------- kernels ----------------

__global__ void k_zero() {
    int i = blockIdx.x * blockDim.x + threadIdx.x;
    if (i < N_NODES * 16) g_agg[i] = 0.f;
    if (i < N_NODES)      g_cnt[i] = 0.f;
}

// y|r = x @ [w1_l | w1_r]   (128 -> 32), weights in shared, f32x2 packed FMA
__global__ void k_gemm_in(const float* __restrict__ x,
                          const float* __restrict__ wl,
                          const float* __restrict__ wr) {
    __shared__ float sw[IN_F * 32];
    for (int i = threadIdx.x; i < IN_F * 32; i += blockDim.x) {
        int k = i >> 5, c = i & 31;
        sw[i] = (c < 16) ? wl[k * 16 + c] : wr[k * 16 + (c - 16)];
    }
    __syncthreads();
    int n = blockIdx.x * blockDim.x + threadIdx.x;
    if (n >= N_NODES) return;

    unsigned long long acc2[16];
#pragma unroll
    for (int j = 0; j < 16; j++) acc2[j] = 0ull;

    const float4* xr = (const float4*)(x + (size_t)n * IN_F);
    const unsigned long long* sw2 = (const unsigned long long*)sw;

#pragma unroll 4
    for (int k4 = 0; k4 < IN_F / 4; k4++) {
        float4 xv = __ldg(xr + k4);
        float xs[4] = {xv.x, xv.y, xv.z, xv.w};
#pragma unroll
        for (int i = 0; i < 4; i++) {
            unsigned long long xx = pack2(xs[i]);
            int k = k4 * 4 + i;
#pragma unroll
            for (int j = 0; j < 16; j++)
                ffma2(acc2[j], xx, sw2[k * 16 + j]);   // uniform smem addr -> broadcast
        }
    }
    ulonglong2* o = (ulonglong2*)(g_yr + (size_t)n * 32);
#pragma unroll
    for (int j = 0; j < 8; j++)
        o[j] = make_ulonglong2(acc2[2 * j], acc2[2 * j + 1]);
}

// generic 16 -> 32 transform from g_h into g_yr.
// sw[k][c] = (c<16) ? wa[k][c] : wb[k+offB][c-16]; optional bias added to cols 0..15.
__global__ void k_gemm16(const float* __restrict__ wa,
                         const float* __restrict__ wb,
                         const float* __restrict__ bias,
                         int offB) {
    __shared__ float sw[16 * 32];
    for (int i = threadIdx.x; i < 16 * 32; i += blockDim.x) {
        int k = i >> 5, c = i & 31;
        sw[i] = (c < 16) ? wa[k * 16 + c] : wb[(k + offB) * 16 + (c - 16)];
    }
    __syncthreads();
    int n = blockIdx.x * blockDim.x + threadIdx.x;
    if (n >= N_NODES) return;

    float acc[32];
#pragma unroll
    for (int j = 0; j < 32; j++) acc[j] = 0.f;

    const float4* hr = (const float4*)(g_h + (size_t)n * 16);
    float4 hv[4];
#pragma unroll
    for (int q = 0; q < 4; q++) hv[q] = hr[q];
    float hrow[16] = {hv[0].x, hv[0].y, hv[0].z, hv[0].w,
                      hv[1].x, hv[1].y, hv[1].z, hv[1].w,
                      hv[2].x, hv[2].y, hv[2].z, hv[2].w,
                      hv[3].x, hv[3].y, hv[3].z, hv[3].w};

    const float4* sw4 = (const float4*)sw;
#pragma unroll
    for (int k = 0; k < 16; k++) {
        float xk = hrow[k];
#pragma unroll
        for (int j = 0; j < 8; j++) {
            float4 w = sw4[k * 8 + j];
            acc[4 * j + 0] = fmaf(xk, w.x, acc[4 * j + 0]);
            acc[4 * j + 1] = fmaf(xk, w.y, acc[4 * j + 1]);
            acc[4 * j + 2] = fmaf(xk, w.z, acc[4 * j + 2]);
            acc[4 * j + 3] = fmaf(xk, w.w, acc[4 * j + 3]);
        }
    }
    if (bias) {
#pragma unroll
        for (int j = 0; j < 16; j++) acc[j] += __ldg(bias + j);
    }
    float4* o = (float4*)(g_yr + (size_t)n * 32);
#pragma unroll
    for (int j = 0; j < 8; j++)
        o[j] = make_float4(acc[4 * j], acc[4 * j + 1], acc[4 * j + 2], acc[4 * j + 3]);
}

// edge scatter: 4 threads per edge, each does one 16B vector red to g_agg[dst]
__global__ void k_scatter(const int* __restrict__ ei, int addCnt) {
    int t = blockIdx.x * blockDim.x + threadIdx.x;
    if (t >= N_EDGES * 4) return;
    int e = t >> 2, c = t & 3;
    int s = __ldg(ei + e);
    int d = __ldg(ei + N_EDGES + e);
    float4 v = *(const float4*)(g_yr + (size_t)s * 32 + 4 * c);  // y part (cols 0..15)
    float* p = g_agg + (size_t)d * 16 + 4 * c;
    asm volatile("red.global.add.v4.f32 [%0], {%1,%2,%3,%4};"
                 :: "l"(p), "f"(v.x), "f"(v.y), "f"(v.z), "f"(v.w) : "memory");
    if (addCnt && c == 0) atomicAdd(g_cnt + d, 1.0f);
}

// h = relu(agg / max(cnt,1) + b_l + r) ; optionally re-zero agg for next layer
__global__ void k_combine(const float* __restrict__ bl, int zeroAgg) {
    int i = blockIdx.x * blockDim.x + threadIdx.x;
    if (i >= N_NODES * 16) return;
    int n = i >> 4, j = i & 15;
    float cnt = fmaxf(g_cnt[n], 1.0f);
    float v = __fdividef(g_agg[i], cnt) + __ldg(bl + j) + g_yr[(size_t)n * 32 + 16 + j];
    g_h[i] = fmaxf(v, 0.f);
    if (zeroAgg) g_agg[i] = 0.f;
}

// per edge, 4 cooperative lanes: z = relu(a[src] + b[dst]) ; o = z @ fc2 + fc2_b ; log_softmax
// lane c in [0,4) handles feature chunk 4c..4c+3; coalesced 16B loads across the warp.
__global__ void k_edge(const int* __restrict__ ei,
                       const float* __restrict__ fc2w,
                       const float* __restrict__ fc2b,
                       float* __restrict__ out) {
    __shared__ float sf[34];
    if (threadIdx.x < 32) sf[threadIdx.x] = fc2w[threadIdx.x];
    if (threadIdx.x < 2)  sf[32 + threadIdx.x] = fc2b[threadIdx.x];
    __syncthreads();
    int t = blockIdx.x * blockDim.x + threadIdx.x;
    if (t >= N_EDGES * 4) return;
    int e = t >> 2, c = t & 3;
    int s = __ldg(ei + e);
    int d = __ldg(ei + N_EDGES + e);
    float4 a = *(const float4*)(g_yr + (size_t)s * 32 + 4 * c);       // a chunk
    float4 b = *(const float4*)(g_yr + (size_t)d * 32 + 16 + 4 * c);  // b chunk
    float z0 = fmaxf(a.x + b.x, 0.f);
    float z1 = fmaxf(a.y + b.y, 0.f);
    float z2 = fmaxf(a.z + b.z, 0.f);
    float z3 = fmaxf(a.w + b.w, 0.f);
    int j = 4 * c;
    float o0, o1;
    o0 = z0 * sf[(j + 0) * 2 + 0];                 o1 = z0 * sf[(j + 0) * 2 + 1];
    o0 = fmaf(z1, sf[(j + 1) * 2 + 0], o0);        o1 = fmaf(z1, sf[(j + 1) * 2 + 1], o1);
    o0 = fmaf(z2, sf[(j + 2) * 2 + 0], o0);        o1 = fmaf(z2, sf[(j + 2) * 2 + 1], o1);
    o0 = fmaf(z3, sf[(j + 3) * 2 + 0], o0);        o1 = fmaf(z3, sf[(j + 3) * 2 + 1], o1);
    // reduce over the 4 lanes of this edge
    o0 += __shfl_xor_sync(~0u, o0, 1);  o1 += __shfl_xor_sync(~0u, o1, 1);
    o0 += __shfl_xor_sync(~0u, o0, 2);  o1 += __shfl_xor_sync(~0u, o1, 2);
    if (c == 0) {
        o0 += sf[32]; o1 += sf[33];
        float m = fmaxf(o0, o1);
        float l = m + __logf(__expf(o0 - m) + __expf(o1 - m));
        ((float2*)out)[e] = make_float2(o0 - l, o1 - l);
    }
}

// ---------------- launch ----------------

extern "C" void kernel_launch(void* const* d_in, const int* in_sizes, int n_in,
                              void* d_out, int out_size) {
    const float* x    = (const float*)d_in[0];
    const int*   ei   = (const int*)  d_in[1];
    const float* w1l  = (const float*)d_in[2];
    const float* b1l  = (const float*)d_in[3];
    const float* w1r  = (const float*)d_in[4];
    const float* w2l  = (const float*)d_in[5];
    const float* b2l  = (const float*)d_in[6];
    const float* w2r  = (const float*)d_in[7];
    const float* fc1w = (const float*)d_in[8];
    const float* fc1b = (const float*)d_in[9];
    const float* fc2w = (const float*)d_in[10];
    const float* fc2b = (const float*)d_in[11];
    float* out = (float*)d_out;

    const int TB = 256;
    int gN16 = (N_NODES * 16 + TB - 1) / TB;   // 6250
    int gG   = (N_NODES + 127) / 128;          // 782
    int gE4  = (N_EDGES * 4 + TB - 1) / TB;    // 50000
    int gN   = (N_NODES + 127) / 128;

    // layer 1
    k_zero<<<gN16, TB>>>();
    k_gemm_in<<<gG, 128>>>(x, w1l, w1r);
    k_scatter<<<gE4, TB>>>(ei, 1);
    k_combine<<<gN16, TB>>>(b1l, 1);   // writes h1, re-zeros agg
    // layer 2
    k_gemm16<<<gN, 128>>>(w2l, w2r, nullptr, 0);
    k_scatter<<<gE4, TB>>>(ei, 0);
    k_combine<<<gN16, TB>>>(b2l, 0);   // writes h2
    // edge MLP precompute: a|b = h2 @ [fc1_top | fc1_bot] (+fc1_b on a)
    k_gemm16<<<gN, 128>>>(fc1w, fc1w, fc1b, 16);
    // per-edge head + log_softmax (4 lanes per edge)
    k_edge<<<gE4, TB>>>(ei, fc2w, fc2b, out);
}

// round 13
// speedup vs baseline: 1.2923x; 1.0404x over previous
#include <cuda_runtime.h>
#include <cstdint>

#define N_NODES 100000
#define N_EDGES 3200000
#define IN_F    128

// ---------------- scratch (no allocations allowed) ----------------
// device globals are zero-initialized at load; every call restores agg/cnt to
// zero before exit, so graph replays see the same initial state.
__device__ float g_yr[N_NODES * 32];    // [n][0:16]=y, [n][16:32]=r ; updated in place each stage
__device__ float g_agg[N_NODES * 16];   // neighbor-sum accumulator (zeroed by fused combine)
__device__ float g_cnt[N_NODES];        // in-degree (zeroed by fused combine #2)

// packed f32x2 FMA (Blackwell; ptxas never emits FFMA2 from C++)
__device__ __forceinline__ void ffma2(unsigned long long& d,
                                      unsigned long long a,
                                      unsigned long long b) {
    asm("fma.rn.f32x2 %0, %1, %2, %0;" : "+l"(d) : "l"(a), "l"(b));
}
__device__ __forceinline__ unsigned long long pack2(float v) {
    unsigned long long r;
    asm("mov.b64 %0, {%1, %1};" : "=l"(r) : "f"(v));
    return r;
}

// ---------------- kernels ----------------

// y|r = x @ [w1_l | w1_r]   (128 -> 32), weights in shared, f32x2 packed FMA
__global__ void k_gemm_in(const float* __restrict__ x,
                          const float* __restrict__ wl,
                          const float* __restrict__ wr) {
    __shared__ float sw[IN_F * 32];
    for (int i = threadIdx.x; i < IN_F * 32; i += blockDim.x) {
        int k = i >> 5, c = i & 31;
        sw[i] = (c < 16) ? wl[k * 16 + c] : wr[k * 16 + (c - 16)];
    }
    __syncthreads();
    int n = blockIdx.x * blockDim.x + threadIdx.x;
    if (n >= N_NODES) return;

    unsigned long long acc2[16];
#pragma unroll
    for (int j = 0; j < 16; j++) acc2[j] = 0ull;

    const float4* xr = (const float4*)(x + (size_t)n * IN_F);
    const unsigned long long* sw2 = (const unsigned long long*)sw;

#pragma unroll 4
    for (int k4 = 0; k4 < IN_F / 4; k4++) {
        float4 xv = __ldg(xr + k4);
        float xs[4] = {xv.x, xv.y, xv.z, xv.w};
#pragma unroll
        for (int i = 0; i < 4; i++) {
            unsigned long long xx = pack2(xs[i]);
            int k = k4 * 4 + i;
#pragma unroll
            for (int j = 0; j < 16; j++)
                ffma2(acc2[j], xx, sw2[k * 16 + j]);   // uniform smem addr -> broadcast
        }
    }
    ulonglong2* o = (ulonglong2*)(g_yr + (size_t)n * 32);
#pragma unroll
    for (int j = 0; j < 8; j++)
        o[j] = make_ulonglong2(acc2[2 * j], acc2[2 * j + 1]);
}

// edge scatter: 4 threads per edge, each does one 16B vector red to g_agg[dst]
__global__ void k_scatter(const int* __restrict__ ei, int addCnt) {
    int t = blockIdx.x * blockDim.x + threadIdx.x;
    if (t >= N_EDGES * 4) return;
    int e = t >> 2, c = t & 3;
    int s = __ldg(ei + e);
    int d = __ldg(ei + N_EDGES + e);
    float4 v = *(const float4*)(g_yr + (size_t)s * 32 + 4 * c);  // y part (cols 0..15)
    float* p = g_agg + (size_t)d * 16 + 4 * c;
    asm volatile("red.global.add.v4.f32 [%0], {%1,%2,%3,%4};"
                 :: "l"(p), "f"(v.x), "f"(v.y), "f"(v.z), "f"(v.w) : "memory");
    if (addCnt && c == 0) atomicAdd(g_cnt + d, 1.0f);
}

// Fused combine + 16->32 GEMM, thread per node, in-place on g_yr:
//   h_j = relu(agg[n][j]/max(cnt,1) + bc[j] + yr[n][16+j])
//   yr[n][c] = sum_k h_k * sw[k][c] (+bo[c] on c<16)
// Re-zeroes agg row (and cnt if zeroCnt) so the next call starts clean.
// sw[k][c] = (c<16) ? wa[k][c] : wb[k+offB][c-16]
__global__ void k_comb16(const float* __restrict__ wa,
                         const float* __restrict__ wb,
                         const float* __restrict__ bc,
                         const float* __restrict__ bo,
                         int offB, int zeroCnt) {
    __shared__ float sw[16 * 32];
    __shared__ float sbc[16], sbo[16];
    for (int i = threadIdx.x; i < 16 * 32; i += blockDim.x) {
        int k = i >> 5, c = i & 31;
        sw[i] = (c < 16) ? wa[k * 16 + c] : wb[(k + offB) * 16 + (c - 16)];
    }
    if (threadIdx.x < 16) {
        sbc[threadIdx.x] = bc[threadIdx.x];
        sbo[threadIdx.x] = bo ? bo[threadIdx.x] : 0.f;
    }
    __syncthreads();
    int n = blockIdx.x * blockDim.x + threadIdx.x;
    if (n >= N_NODES) return;

    // load agg row + residual chunk, compute h in registers
    float4* ag = (float4*)(g_agg + (size_t)n * 16);
    const float4* rr = (const float4*)(g_yr + (size_t)n * 32 + 16);
    float cnt = g_cnt[n];
    float inv = __fdividef(1.f, fmaxf(cnt, 1.f));

    float h[16];
#pragma unroll
    for (int q = 0; q < 4; q++) {
        float4 a = ag[q];
        float4 r = rr[q];
        h[4 * q + 0] = fmaxf(fmaf(a.x, inv, sbc[4 * q + 0] + r.x), 0.f);
        h[4 * q + 1] = fmaxf(fmaf(a.y, inv, sbc[4 * q + 1] + r.y), 0.f);
        h[4 * q + 2] = fmaxf(fmaf(a.z, inv, sbc[4 * q + 2] + r.z), 0.f);
        h[4 * q + 3] = fmaxf(fmaf(a.w, inv, sbc[4 * q + 3] + r.w), 0.f);
    }
    // restore invariant for next graph replay
    float4 z4 = make_float4(0.f, 0.f, 0.f, 0.f);
#pragma unroll
    for (int q = 0; q < 4; q++) ag[q] = z4;
    if (zeroCnt) g_cnt[n] = 0.f;

    // 16 -> 32 GEMM from shared weights
    float acc[32];
#pragma unroll
    for (int j = 0; j < 32; j++) acc[j] = 0.f;
    const float4* sw4 = (const float4*)sw;
#pragma unroll
    for (int k = 0; k < 16; k++) {
        float xk = h[k];
#pragma unroll
        for (int j = 0; j < 8; j++) {
            float4 w = sw4[k * 8 + j];
            acc[4 * j + 0] = fmaf(xk, w.x, acc[4 * j + 0]);
            acc[4 * j + 1] = fmaf(xk, w.y, acc[4 * j + 1]);
            acc[4 * j + 2] = fmaf(xk, w.z, acc[4 * j + 2]);
            acc[4 * j + 3] = fmaf(xk, w.w, acc[4 * j + 3]);
        }
    }
#pragma unroll
    for (int j = 0; j < 16; j++) acc[j] += sbo[j];

    float4* o = (float4*)(g_yr + (size_t)n * 32);   // in-place: row n read+written by this thread only
#pragma unroll
    for (int j = 0; j < 8; j++)
        o[j] = make_float4(acc[4 * j], acc[4 * j + 1], acc[4 * j + 2], acc[4 * j + 3]);
}

// per edge, 4 cooperative lanes: z = relu(a[src] + b[dst]) ; o = z @ fc2 + fc2_b ; log_softmax
__global__ void k_edge(const int* __restrict__ ei,
                       const float* __restrict__ fc2w,
                       const float* __restrict__ fc2b,
                       float* __restrict__ out) {
    __shared__ float sf[34];
    if (threadIdx.x < 32) sf[threadIdx.x] = fc2w[threadIdx.x];
    if (threadIdx.x < 2)  sf[32 + threadIdx.x] = fc2b[threadIdx.x];
    __syncthreads();
    int t = blockIdx.x * blockDim.x + threadIdx.x;
    if (t >= N_EDGES * 4) return;
    int e = t >> 2, c = t & 3;
    int s = __ldg(ei + e);
    int d = __ldg(ei + N_EDGES + e);
    float4 a = *(const float4*)(g_yr + (size_t)s * 32 + 4 * c);       // a chunk
    float4 b = *(const float4*)(g_yr + (size_t)d * 32 + 16 + 4 * c);  // b chunk
    float z0 = fmaxf(a.x + b.x, 0.f);
    float z1 = fmaxf(a.y + b.y, 0.f);
    float z2 = fmaxf(a.z + b.z, 0.f);
    float z3 = fmaxf(a.w + b.w, 0.f);
    int j = 4 * c;
    float o0, o1;
    o0 = z0 * sf[(j + 0) * 2 + 0];                 o1 = z0 * sf[(j + 0) * 2 + 1];
    o0 = fmaf(z1, sf[(j + 1) * 2 + 0], o0);        o1 = fmaf(z1, sf[(j + 1) * 2 + 1], o1);
    o0 = fmaf(z2, sf[(j + 2) * 2 + 0], o0);        o1 = fmaf(z2, sf[(j + 2) * 2 + 1], o1);
    o0 = fmaf(z3, sf[(j + 3) * 2 + 0], o0);        o1 = fmaf(z3, sf[(j + 3) * 2 + 1], o1);
    // reduce over the 4 lanes of this edge
    o0 += __shfl_xor_sync(~0u, o0, 1);  o1 += __shfl_xor_sync(~0u, o1, 1);
    o0 += __shfl_xor_sync(~0u, o0, 2);  o1 += __shfl_xor_sync(~0u, o1, 2);
    if (c == 0) {
        o0 += sf[32]; o1 += sf[33];
        float m = fmaxf(o0, o1);
        float l = m + __logf(__expf(o0 - m) + __expf(o1 - m));
        ((float2*)out)[e] = make_float2(o0 - l, o1 - l);
    }
}

// ---------------- launch ----------------

extern "C" void kernel_launch(void* const* d_in, const int* in_sizes, int n_in,
                              void* d_out, int out_size) {
    const float* x    = (const float*)d_in[0];
    const int*   ei   = (const int*)  d_in[1];
    const float* w1l  = (const float*)d_in[2];
    const float* b1l  = (const float*)d_in[3];
    const float* w1r  = (const float*)d_in[4];
    const float* w2l  = (const float*)d_in[5];
    const float* b2l  = (const float*)d_in[6];
    const float* w2r  = (const float*)d_in[7];
    const float* fc1w = (const float*)d_in[8];
    const float* fc1b = (const float*)d_in[9];
    const float* fc2w = (const float*)d_in[10];
    const float* fc2b = (const float*)d_in[11];
    float* out = (float*)d_out;

    const int TB = 256;
    int gG  = (N_NODES + 127) / 128;          // 782, thread-per-node kernels
    int gE4 = (N_EDGES * 4 + TB - 1) / TB;    // 50000

    // A = x @ [w1_l|w1_r]
    k_gemm_in<<<gG, 128>>>(x, w1l, w1r);
    // layer 1: scatter y -> agg (+cnt); fused combine+GEMM -> y|r (in place), zero agg
    k_scatter<<<gE4, TB>>>(ei, 1);
    k_comb16<<<gG, 128>>>(w2l, w2r, b1l, nullptr, 0, 0);
    // layer 2: scatter y -> agg; fused combine+GEMM with fc1 -> a|b, zero agg + cnt
    k_scatter<<<gE4, TB>>>(ei, 0);
    k_comb16<<<gG, 128>>>(fc1w, fc1w, b2l, fc1b, 16, 1);
    // per-edge head + log_softmax (4 lanes per edge)
    k_edge<<<gE4, TB>>>(ei, fc2w, fc2b, out);
}

// round 14
// speedup vs baseline: 1.2935x; 1.0009x over previous
#include <cuda_runtime.h>
#include <cstdint>

#define N_NODES 100000
#define N_EDGES 3200000
#define IN_F    128

// ---------------- scratch (no allocations allowed) ----------------
// device globals are zero-initialized at load; every call restores agg/cnt to
// zero before exit, so graph replays see the same initial state.
__device__ float g_yr[N_NODES * 32];    // [n][0:16]=y, [n][16:32]=r ; updated in place each stage
__device__ float g_agg[N_NODES * 16];   // neighbor-sum accumulator (zeroed by fused combine)
__device__ float g_cnt[N_NODES];        // in-degree (zeroed by fused combine #2)

// packed f32x2 FMA (Blackwell; ptxas never emits FFMA2 from C++)
__device__ __forceinline__ void ffma2(unsigned long long& d,
                                      unsigned long long a,
                                      unsigned long long b) {
    asm("fma.rn.f32x2 %0, %1, %2, %0;" : "+l"(d) : "l"(a), "l"(b));
}
__device__ __forceinline__ unsigned long long pack2(float v) {
    unsigned long long r;
    asm("mov.b64 %0, {%1, %1};" : "=l"(r) : "f"(v));
    return r;
}

// PDL: wait for programmatic predecessor's trigger (+mem visibility);
// trigger allows dependents to launch once ALL threads triggered or exited.
__device__ __forceinline__ void pdl_wait() {
    asm volatile("griddepcontrol.wait;" ::: "memory");
}
__device__ __forceinline__ void pdl_trigger() {
    asm volatile("griddepcontrol.launch_dependents;" ::: "memory");
}

// ---------------- kernels ----------------

// y|r = x @ [w1_l | w1_r]   (128 -> 32), weights in shared, f32x2 packed FMA
__global__ void k_gemm_in(const float* __restrict__ x,
                          const float* __restrict__ wl,
                          const float* __restrict__ wr) {
    __shared__ float sw[IN_F * 32];
    for (int i = threadIdx.x; i < IN_F * 32; i += blockDim.x) {
        int k = i >> 5, c = i & 31;
        sw[i] = (c < 16) ? wl[k * 16 + c] : wr[k * 16 + (c - 16)];
    }
    __syncthreads();
    int n = blockIdx.x * blockDim.x + threadIdx.x;
    if (n >= N_NODES) { pdl_trigger(); return; }

    unsigned long long acc2[16];
#pragma unroll
    for (int j = 0; j < 16; j++) acc2[j] = 0ull;

    const float4* xr = (const float4*)(x + (size_t)n * IN_F);
    const unsigned long long* sw2 = (const unsigned long long*)sw;

#pragma unroll 4
    for (int k4 = 0; k4 < IN_F / 4; k4++) {
        float4 xv = __ldg(xr + k4);
        float xs[4] = {xv.x, xv.y, xv.z, xv.w};
#pragma unroll
        for (int i = 0; i < 4; i++) {
            unsigned long long xx = pack2(xs[i]);
            int k = k4 * 4 + i;
#pragma unroll
            for (int j = 0; j < 16; j++)
                ffma2(acc2[j], xx, sw2[k * 16 + j]);   // uniform smem addr -> broadcast
        }
    }
    ulonglong2* o = (ulonglong2*)(g_yr + (size_t)n * 32);
#pragma unroll
    for (int j = 0; j < 8; j++)
        o[j] = make_ulonglong2(acc2[2 * j], acc2[2 * j + 1]);
    pdl_trigger();
}

// edge scatter: 4 threads per edge, each does one 16B vector red to g_agg[dst]
__global__ void k_scatter(const int* __restrict__ ei, int addCnt) {
    int t = blockIdx.x * blockDim.x + threadIdx.x;
    if (t >= N_EDGES * 4) return;              // exit counts as trigger
    int e = t >> 2, c = t & 3;
    int s = __ldg(ei + e);                     // harness input: safe pre-wait
    int d = __ldg(ei + N_EDGES + e);
    pdl_wait();                                // g_yr / zeroed g_agg ready
    float4 v = *(const float4*)(g_yr + (size_t)s * 32 + 4 * c);  // y part (cols 0..15)
    float* p = g_agg + (size_t)d * 16 + 4 * c;
    asm volatile("red.global.add.v4.f32 [%0], {%1,%2,%3,%4};"
                 :: "l"(p), "f"(v.x), "f"(v.y), "f"(v.z), "f"(v.w) : "memory");
    if (addCnt && c == 0) atomicAdd(g_cnt + d, 1.0f);
    pdl_trigger();
}

// Fused combine + 16->32 GEMM, thread per node, in-place on g_yr:
//   h_j = relu(agg[n][j]/max(cnt,1) + bc[j] + yr[n][16+j])
//   yr[n][c] = sum_k h_k * sw[k][c] (+bo[c] on c<16)
// Re-zeroes agg row (and cnt if zeroCnt) so the next call starts clean.
// sw[k][c] = (c<16) ? wa[k][c] : wb[k+offB][c-16]
__global__ void k_comb16(const float* __restrict__ wa,
                         const float* __restrict__ wb,
                         const float* __restrict__ bc,
                         const float* __restrict__ bo,
                         int offB, int zeroCnt) {
    __shared__ float sw[16 * 32];
    __shared__ float sbc[16], sbo[16];
    for (int i = threadIdx.x; i < 16 * 32; i += blockDim.x) {
        int k = i >> 5, c = i & 31;
        sw[i] = (c < 16) ? wa[k * 16 + c] : wb[(k + offB) * 16 + (c - 16)];
    }
    if (threadIdx.x < 16) {
        sbc[threadIdx.x] = bc[threadIdx.x];
        sbo[threadIdx.x] = bo ? bo[threadIdx.x] : 0.f;
    }
    __syncthreads();                            // weight staging overlaps predecessor
    int n = blockIdx.x * blockDim.x + threadIdx.x;
    if (n >= N_NODES) { pdl_trigger(); return; }
    pdl_wait();                                 // agg/cnt complete

    // load agg row + residual chunk, compute h in registers
    float4* ag = (float4*)(g_agg + (size_t)n * 16);
    const float4* rr = (const float4*)(g_yr + (size_t)n * 32 + 16);
    float cnt = g_cnt[n];
    float inv = __fdividef(1.f, fmaxf(cnt, 1.f));

    float h[16];
#pragma unroll
    for (int q = 0; q < 4; q++) {
        float4 a = ag[q];
        float4 r = rr[q];
        h[4 * q + 0] = fmaxf(fmaf(a.x, inv, sbc[4 * q + 0] + r.x), 0.f);
        h[4 * q + 1] = fmaxf(fmaf(a.y, inv, sbc[4 * q + 1] + r.y), 0.f);
        h[4 * q + 2] = fmaxf(fmaf(a.z, inv, sbc[4 * q + 2] + r.z), 0.f);
        h[4 * q + 3] = fmaxf(fmaf(a.w, inv, sbc[4 * q + 3] + r.w), 0.f);
    }
    // restore invariant for next stage / replay
    float4 z4 = make_float4(0.f, 0.f, 0.f, 0.f);
#pragma unroll
    for (int q = 0; q < 4; q++) ag[q] = z4;
    if (zeroCnt) g_cnt[n] = 0.f;

    // 16 -> 32 GEMM from shared weights
    float acc[32];
#pragma unroll
    for (int j = 0; j < 32; j++) acc[j] = 0.f;
    const float4* sw4 = (const float4*)sw;
#pragma unroll
    for (int k = 0; k < 16; k++) {
        float xk = h[k];
#pragma unroll
        for (int j = 0; j < 8; j++) {
            float4 w = sw4[k * 8 + j];
            acc[4 * j + 0] = fmaf(xk, w.x, acc[4 * j + 0]);
            acc[4 * j + 1] = fmaf(xk, w.y, acc[4 * j + 1]);
            acc[4 * j + 2] = fmaf(xk, w.z, acc[4 * j + 2]);
            acc[4 * j + 3] = fmaf(xk, w.w, acc[4 * j + 3]);
        }
    }
#pragma unroll
    for (int j = 0; j < 16; j++) acc[j] += sbo[j];

    float4* o = (float4*)(g_yr + (size_t)n * 32);   // in-place: row n read+written by this thread only
#pragma unroll
    for (int j = 0; j < 8; j++)
        o[j] = make_float4(acc[4 * j], acc[4 * j + 1], acc[4 * j + 2], acc[4 * j + 3]);
    pdl_trigger();
}

// per edge, 4 cooperative lanes: z = relu(a[src] + b[dst]) ; o = z @ fc2 + fc2_b ; log_softmax
__global__ void k_edge(const int* __restrict__ ei,
                       const float* __restrict__ fc2w,
                       const float* __restrict__ fc2b,
                       float* __restrict__ out) {
    __shared__ float sf[34];
    if (threadIdx.x < 32) sf[threadIdx.x] = fc2w[threadIdx.x];
    if (threadIdx.x < 2)  sf[32 + threadIdx.x] = fc2b[threadIdx.x];
    __syncthreads();
    int t = blockIdx.x * blockDim.x + threadIdx.x;
    if (t >= N_EDGES * 4) return;
    int e = t >> 2, c = t & 3;
    int s = __ldg(ei + e);
    int d = __ldg(ei + N_EDGES + e);
    pdl_wait();                                  // a|b table complete
    float4 a = *(const float4*)(g_yr + (size_t)s * 32 + 4 * c);       // a chunk
    float4 b = *(const float4*)(g_yr + (size_t)d * 32 + 16 + 4 * c);  // b chunk
    float z0 = fmaxf(a.x + b.x, 0.f);
    float z1 = fmaxf(a.y + b.y, 0.f);
    float z2 = fmaxf(a.z + b.z, 0.f);
    float z3 = fmaxf(a.w + b.w, 0.f);
    int j = 4 * c;
    float o0, o1;
    o0 = z0 * sf[(j + 0) * 2 + 0];                 o1 = z0 * sf[(j + 0) * 2 + 1];
    o0 = fmaf(z1, sf[(j + 1) * 2 + 0], o0);        o1 = fmaf(z1, sf[(j + 1) * 2 + 1], o1);
    o0 = fmaf(z2, sf[(j + 2) * 2 + 0], o0);        o1 = fmaf(z2, sf[(j + 2) * 2 + 1], o1);
    o0 = fmaf(z3, sf[(j + 3) * 2 + 0], o0);        o1 = fmaf(z3, sf[(j + 3) * 2 + 1], o1);
    // reduce over the 4 lanes of this edge
    o0 += __shfl_xor_sync(~0u, o0, 1);  o1 += __shfl_xor_sync(~0u, o1, 1);
    o0 += __shfl_xor_sync(~0u, o0, 2);  o1 += __shfl_xor_sync(~0u, o1, 2);
    if (c == 0) {
        o0 += sf[32]; o1 += sf[33];
        float m = fmaxf(o0, o1);
        float l = m + __logf(__expf(o0 - m) + __expf(o1 - m));
        ((float2*)out)[e] = make_float2(o0 - l, o1 - l);
    }
}

// ---------------- launch ----------------

template <typename... Args>
static void launch_pdl(void (*kern)(Args...), dim3 grid, dim3 block, Args... args) {
    cudaLaunchConfig_t cfg = {};
    cfg.gridDim = grid;
    cfg.blockDim = block;
    cfg.stream = 0;   // same (legacy default) stream as <<<>>> launches
    cudaLaunchAttribute attr[1];
    attr[0].id = cudaLaunchAttributeProgrammaticStreamSerialization;
    attr[0].val.programmaticStreamSerializationAllowed = 1;
    cfg.attrs = attr;
    cfg.numAttrs = 1;
    cudaLaunchKernelEx(&cfg, kern, args...);
}

extern "C" void kernel_launch(void* const* d_in, const int* in_sizes, int n_in,
                              void* d_out, int out_size) {
    const float* x    = (const float*)d_in[0];
    const int*   ei   = (const int*)  d_in[1];
    const float* w1l  = (const float*)d_in[2];
    const float* b1l  = (const float*)d_in[3];
    const float* w1r  = (const float*)d_in[4];
    const float* w2l  = (const float*)d_in[5];
    const float* b2l  = (const float*)d_in[6];
    const float* w2r  = (const float*)d_in[7];
    const float* fc1w = (const float*)d_in[8];
    const float* fc1b = (const float*)d_in[9];
    const float* fc2w = (const float*)d_in[10];
    const float* fc2b = (const float*)d_in[11];
    float* out = (float*)d_out;

    const int TB = 256;
    int gG  = (N_NODES + 127) / 128;          // 782, thread-per-node kernels
    int gE4 = (N_EDGES * 4 + TB - 1) / TB;    // 50000

    // A = x @ [w1_l|w1_r]  (normal launch: full order vs previous replay's k_edge)
    k_gemm_in<<<gG, 128>>>(x, w1l, w1r);
    // layer 1: scatter y -> agg (+cnt); fused combine+GEMM -> y|r (in place), zero agg
    launch_pdl(k_scatter, dim3(gE4), dim3(TB), ei, 1);
    launch_pdl(k_comb16, dim3(gG), dim3(128), w2l, w2r, b1l, (const float*)nullptr, 0, 0);
    // layer 2: scatter y -> agg; fused combine+GEMM with fc1 -> a|b, zero agg + cnt
    launch_pdl(k_scatter, dim3(gE4), dim3(TB), ei, 0);
    launch_pdl(k_comb16, dim3(gG), dim3(128), fc1w, fc1w, b2l, fc1b, 16, 1);
    // per-edge head + log_softmax (4 lanes per edge)
    launch_pdl(k_edge, dim3(gE4), dim3(TB), ei, fc2w, fc2b, out);
}